// round 10
// baseline (speedup 1.0000x reference)
#include <cuda_runtime.h>
#include <cuda_bf16.h>
#include <cstdint>

#define N_NODES 20000
#define N_EDGES 320000
#define D_IN    300
#define EMB     256

// ---------------- scratch (device globals; no allocation allowed) ----------
__device__ float g_tmp[N_NODES * EMB];
__device__ float g_dinv[N_NODES];
__device__ int   g_cnt [N_NODES];
__device__ int   g_rowptr[N_NODES + 1];
__device__ int   g_fill[N_NODES];
__device__ int   g_srcs[N_EDGES];
__device__ __align__(16) __nv_bfloat16 g_bufA[N_NODES * 640];
__device__ __align__(16) __nv_bfloat16 g_bufB[N_NODES * 640];
__device__ __align__(16) __nv_bfloat16 g_w2[6 * 256 * 640];

// ---------------- PTX helpers ----------------------------------------------
__device__ __forceinline__ uint32_t smem_u32(const void* p) {
    uint32_t a;
    asm("{ .reg .u64 t; cvta.to.shared.u64 t, %1; cvt.u32.u64 %0, t; }"
        : "=r"(a) : "l"(p));
    return a;
}
#define CP_ASYNC16Z(dst, src, sz) \
    asm volatile("cp.async.cg.shared.global [%0], [%1], 16, %2;" \
                 :: "r"(dst), "l"(src), "r"(sz) : "memory")
#define CP_ASYNC16(dst, src) \
    asm volatile("cp.async.cg.shared.global [%0], [%1], 16;" \
                 :: "r"(dst), "l"(src) : "memory")
#define CP_COMMIT() asm volatile("cp.async.commit_group;" ::: "memory")
#define CP_WAIT2()  asm volatile("cp.async.wait_group 2;" ::: "memory")
#define CP_WAIT1()  asm volatile("cp.async.wait_group 1;" ::: "memory")
#define CP_WAIT0()  asm volatile("cp.async.wait_group 0;" ::: "memory")
#define LDM_X4(r0, r1, r2, r3, a) \
    asm volatile("ldmatrix.sync.aligned.m8n8.x4.shared.b16 {%0,%1,%2,%3}, [%4];" \
                 : "=r"(r0), "=r"(r1), "=r"(r2), "=r"(r3) : "r"(a))
#define MMA16816(d, a, b0v, b1v) \
    asm volatile("mma.sync.aligned.m16n8k16.row.col.f32.bf16.bf16.f32 " \
                 "{%0,%1,%2,%3},{%4,%5,%6,%7},{%8,%9},{%0,%1,%2,%3};" \
                 : "+f"((d)[0]), "+f"((d)[1]), "+f"((d)[2]), "+f"((d)[3]) \
                 : "r"((a)[0]), "r"((a)[1]), "r"((a)[2]), "r"((a)[3]), \
                   "r"(b0v), "r"(b1v))

__device__ __forceinline__ void split_bf16(float x, __nv_bfloat16& hi,
                                           __nv_bfloat16& lo) {
    hi = __float2bfloat16_rn(x);
    lo = __float2bfloat16_rn(x - __bfloat162float(hi));
}
union Pack4 { __nv_bfloat16 h[4]; uint2 u; };
union Pack2 { __nv_bfloat16 h[2]; uint32_t u; };

// ---------------- CSR build -------------------------------------------------
__global__ void cnt_zero_kernel() {
    int i = blockIdx.x * blockDim.x + threadIdx.x;
    if (i < N_NODES) g_cnt[i] = 0;
}
__global__ void hist_kernel(const int* __restrict__ ei) {
    int e = blockIdx.x * blockDim.x + threadIdx.x;
    if (e < N_EDGES) atomicAdd(&g_cnt[ei[N_EDGES + e]], 1);
}
// fast block scan: each thread serially owns 20 elements, warp-shuffle scan
__global__ void __launch_bounds__(1024) scan_kernel() {
    const int PER = 20;    // 1024*20 = 20480 >= N_NODES
    int tid = threadIdx.x;
    int lane = tid & 31, wid = tid >> 5;
    int base = tid * PER;
    int sum = 0;
#pragma unroll
    for (int i = 0; i < PER; i++) {
        int idx = base + i;
        if (idx < N_NODES) sum += g_cnt[idx];
    }
    int tot = sum;
#pragma unroll
    for (int o = 1; o < 32; o <<= 1) {
        int n = __shfl_up_sync(0xFFFFFFFFu, tot, o);
        if (lane >= o) tot += n;
    }
    __shared__ int wsum[32];
    if (lane == 31) wsum[wid] = tot;
    __syncthreads();
    if (wid == 0) {
        int v = wsum[lane];
#pragma unroll
        for (int o = 1; o < 32; o <<= 1) {
            int n = __shfl_up_sync(0xFFFFFFFFu, v, o);
            if (lane >= o) v += n;
        }
        wsum[lane] = v;
    }
    __syncthreads();
    int off = (wid ? wsum[wid - 1] : 0) + (tot - sum);  // exclusive offset
    if (tid == 0) g_rowptr[0] = 0;
    int run = off;
#pragma unroll
    for (int i = 0; i < PER; i++) {
        int idx = base + i;
        if (idx < N_NODES) {
            int v = g_cnt[idx];
            run += v;
            g_rowptr[idx + 1] = run;
            g_fill[idx]       = run - v;
            g_dinv[idx]       = rsqrtf((float)v + 1.0f);
        }
    }
}
__global__ void scatter_kernel(const int* __restrict__ ei) {
    int e = blockIdx.x * blockDim.x + threadIdx.x;
    if (e < N_EDGES) {
        int s = ei[e];
        int d = ei[N_EDGES + e];
        int pos = atomicAdd(&g_fill[d], 1);
        g_srcs[pos] = s;
    }
}

// ---------------- aggregation (pull) + fused relu + split-bf16 output ------
template<int RELU>
__global__ void __launch_bounds__(256)
agg_kernel(const float* __restrict__ tmp, const float* __restrict__ bias,
           __nv_bfloat16* __restrict__ outS) {
    int warp = (blockIdx.x * blockDim.x + threadIdx.x) >> 5;
    int lane = threadIdx.x & 31;
    if (warp >= N_NODES) return;
    float dd = g_dinv[warp];
    float ws = dd * dd;
    const float4* tp = reinterpret_cast<const float4*>(tmp);
    const float4* bp = reinterpret_cast<const float4*>(bias);
    long rb = (long)warp * 64;
    float4 b0 = bp[lane], b1 = bp[lane + 32];
    float4 t0 = tp[rb + lane], t1 = tp[rb + 32 + lane];
    float4 a0, a1;
    a0.x = fmaf(t0.x, ws, b0.x); a0.y = fmaf(t0.y, ws, b0.y);
    a0.z = fmaf(t0.z, ws, b0.z); a0.w = fmaf(t0.w, ws, b0.w);
    a1.x = fmaf(t1.x, ws, b1.x); a1.y = fmaf(t1.y, ws, b1.y);
    a1.z = fmaf(t1.z, ws, b1.z); a1.w = fmaf(t1.w, ws, b1.w);
    int e = g_rowptr[warp], end = g_rowptr[warp + 1];
    for (; e + 1 < end; e += 2) {
        int s0 = g_srcs[e], s1 = g_srcs[e + 1];
        float w0 = g_dinv[s0] * dd, w1 = g_dinv[s1] * dd;
        long sb0 = (long)s0 * 64, sb1 = (long)s1 * 64;
        float4 u0 = tp[sb0 + lane], u1 = tp[sb0 + 32 + lane];
        float4 v0 = tp[sb1 + lane], v1 = tp[sb1 + 32 + lane];
        a0.x = fmaf(u0.x, w0, a0.x); a0.y = fmaf(u0.y, w0, a0.y);
        a0.z = fmaf(u0.z, w0, a0.z); a0.w = fmaf(u0.w, w0, a0.w);
        a1.x = fmaf(u1.x, w0, a1.x); a1.y = fmaf(u1.y, w0, a1.y);
        a1.z = fmaf(u1.z, w0, a1.z); a1.w = fmaf(u1.w, w0, a1.w);
        a0.x = fmaf(v0.x, w1, a0.x); a0.y = fmaf(v0.y, w1, a0.y);
        a0.z = fmaf(v0.z, w1, a0.z); a0.w = fmaf(v0.w, w1, a0.w);
        a1.x = fmaf(v1.x, w1, a1.x); a1.y = fmaf(v1.y, w1, a1.y);
        a1.z = fmaf(v1.z, w1, a1.z); a1.w = fmaf(v1.w, w1, a1.w);
    }
    if (e < end) {
        int s0 = g_srcs[e];
        float w0 = g_dinv[s0] * dd;
        long sb0 = (long)s0 * 64;
        float4 u0 = tp[sb0 + lane], u1 = tp[sb0 + 32 + lane];
        a0.x = fmaf(u0.x, w0, a0.x); a0.y = fmaf(u0.y, w0, a0.y);
        a0.z = fmaf(u0.z, w0, a0.z); a0.w = fmaf(u0.w, w0, a0.w);
        a1.x = fmaf(u1.x, w0, a1.x); a1.y = fmaf(u1.y, w0, a1.y);
        a1.z = fmaf(u1.z, w0, a1.z); a1.w = fmaf(u1.w, w0, a1.w);
    }
    if (RELU) {
        a0.x = fmaxf(a0.x, 0.f); a0.y = fmaxf(a0.y, 0.f);
        a0.z = fmaxf(a0.z, 0.f); a0.w = fmaxf(a0.w, 0.f);
        a1.x = fmaxf(a1.x, 0.f); a1.y = fmaxf(a1.y, 0.f);
        a1.z = fmaxf(a1.z, 0.f); a1.w = fmaxf(a1.w, 0.f);
    }
    __nv_bfloat16* rp = outS + (size_t)warp * 512;
    float vs[2][4] = {{a0.x, a0.y, a0.z, a0.w}, {a1.x, a1.y, a1.z, a1.w}};
    int cols[2] = {4 * lane, 128 + 4 * lane};
#pragma unroll
    for (int h = 0; h < 2; h++) {
        Pack4 hi4, lo4;
#pragma unroll
        for (int q = 0; q < 4; q++) split_bf16(vs[h][q], hi4.h[q], lo4.h[q]);
        *reinterpret_cast<uint2*>(rp + cols[h])       = hi4.u;
        *reinterpret_cast<uint2*>(rp + 256 + cols[h]) = lo4.u;
    }
}

// ---------------- x -> split-bf16 -------------------------------------------
__global__ void a2x_kernel(const float* __restrict__ src,
                           __nv_bfloat16* __restrict__ dst) {
    const int Kp = 320;
    int idx = blockIdx.x * blockDim.x + threadIdx.x;
    if (idx >= N_NODES * Kp) return;
    int m = idx / Kp, k = idx - m * Kp;
    __nv_bfloat16 hi = __float2bfloat16_rn(0.f), lo = hi;
    if (k < D_IN) split_bf16(src[(size_t)m * D_IN + k], hi, lo);
    size_t rb = (size_t)m * 640;
    dst[rb + k]      = hi;
    dst[rb + Kp + k] = lo;
}

// ---------------- weights -> split-bf16 -------------------------------------
__global__ void wconv_kernel(const float* __restrict__ W0,
                             const float* __restrict__ W1,
                             const float* __restrict__ W2,
                             const float* __restrict__ M1,
                             const float* __restrict__ M2,
                             const float* __restrict__ M3) {
    int idx = blockIdx.x * blockDim.x + threadIdx.x;
    const float* srcs[6] = {W0, W1, W2, M1, M2, M3};
    int slot, n, k, K, Kp;
    if (idx < 256 * 320) {
        slot = 0; n = idx / 320; k = idx - n * 320; K = D_IN; Kp = 320;
    } else {
        int r = idx - 256 * 320;
        if (r >= 5 * 256 * 256) return;
        slot = 1 + r / 65536; int q = r & 65535;
        n = q >> 8; k = q & 255; K = 256; Kp = 256;
    }
    __nv_bfloat16 hi = __float2bfloat16_rn(0.f), lo = hi;
    if (k < K) split_bf16(srcs[slot][(size_t)k * 256 + n], hi, lo);
    __nv_bfloat16* dst = g_w2 + (size_t)slot * 163840 + (size_t)n * 2 * Kp;
    dst[k]      = hi;
    dst[Kp + k] = lo;
}

// ---------------- bf16 HMMA GEMM (3-stage, occ=2) ---------------------------
#define ROWB 80
#define ATILE (128 * ROWB)
#define STAGEB (2 * ATILE)        // A + B per stage = 20480
#define SMEM_DYN (3 * STAGEB)     // 61440

template<bool HAS_BIAS, bool RELU_OUT, bool WRITE_SPLIT>
__global__ void __launch_bounds__(256, 2)
hgemm_kernel(const __nv_bfloat16* __restrict__ A2,
             const __nv_bfloat16* __restrict__ B2,
             const float* __restrict__ bias,
             float* __restrict__ C, __nv_bfloat16* __restrict__ Cs,
             int M, int Kp) {
    extern __shared__ __align__(128) char sm[];

    int tid  = threadIdx.x;
    int wid  = tid >> 5;
    int lane = tid & 31;
    int bm = blockIdx.x * 128;
    int bn = blockIdx.y * 128;
    int wm = wid & 3;
    int wn = wid >> 2;
    int nseg = Kp >> 5;
    int NK = 3 * nseg;
    int KS = 2 * Kp;

    uint32_t sbase = smem_u32(sm);

    auto issue = [&](int c) {
        int buf = c % 3;
        int seg = c / nseg, kc = c - seg * nseg;
        int ka = ((seg == 1) ? Kp : 0) + kc * 32;
        int kb = ((seg == 2) ? Kp : 0) + kc * 32;
        uint32_t aB = sbase + buf * STAGEB;
        uint32_t bB = aB + ATILE;
#pragma unroll
        for (int i = 0; i < 2; i++) {
            int u = tid + i * 256;
            int r = u >> 2, un = u & 3;
            uint32_t dst = aB + r * ROWB + un * 16;
            const __nv_bfloat16* src = A2 + (size_t)(bm + r) * KS + ka + un * 8;
            int sz = (bm + r < M) ? 16 : 0;
            CP_ASYNC16Z(dst, src, sz);
        }
#pragma unroll
        for (int i = 0; i < 2; i++) {
            int u = tid + i * 256;
            int r = u >> 2, un = u & 3;
            uint32_t dst = bB + r * ROWB + un * 16;
            const __nv_bfloat16* src = B2 + (size_t)(bn + r) * KS + kb + un * 8;
            CP_ASYNC16(dst, src);
        }
        CP_COMMIT();
    };

    float acc[2][8][4];
#pragma unroll
    for (int mt = 0; mt < 2; mt++)
#pragma unroll
        for (int nt = 0; nt < 8; nt++)
#pragma unroll
            for (int q = 0; q < 4; q++) acc[mt][nt][q] = 0.f;

    issue(0);
    issue(1);
    for (int c = 0; c < NK; c++) {
        if (c + 2 < NK)      { issue(c + 2); CP_WAIT2(); }
        else if (c + 1 < NK) { CP_WAIT1(); }
        else                 { CP_WAIT0(); }
        __syncthreads();

        uint32_t aB = sbase + (c % 3) * STAGEB;
        uint32_t bB = aB + ATILE;

        // process N-tiles in halves of 4 to bound live registers (occ=2)
#pragma unroll
        for (int nh = 0; nh < 2; nh++) {
            uint32_t breg[4][4];
#pragma unroll
            for (int n4 = 0; n4 < 4; n4++) {
                int nt = nh * 4 + n4;
                uint32_t addr = bB + (uint32_t)((wn * 64 + nt * 8 + (lane & 7)) * ROWB
                                                + (lane >> 3) * 16);
                LDM_X4(breg[n4][0], breg[n4][1], breg[n4][2], breg[n4][3], addr);
            }
#pragma unroll
            for (int kt = 0; kt < 2; kt++) {
                uint32_t areg[2][4];
#pragma unroll
                for (int mt = 0; mt < 2; mt++) {
                    uint32_t addr = aB + (uint32_t)((wm * 32 + mt * 16 + (lane & 15)) * ROWB
                                                    + (kt * 2 + (lane >> 4)) * 16);
                    LDM_X4(areg[mt][0], areg[mt][1], areg[mt][2], areg[mt][3], addr);
                }
#pragma unroll
                for (int mt = 0; mt < 2; mt++)
#pragma unroll
                    for (int n4 = 0; n4 < 4; n4++)
                        MMA16816(acc[mt][nh * 4 + n4], areg[mt],
                                 breg[n4][kt * 2], breg[n4][kt * 2 + 1]);
            }
        }
        __syncthreads();
    }

    // epilogue
    int gid = lane >> 2, tig = lane & 3;
#pragma unroll
    for (int mt = 0; mt < 2; mt++) {
        int row0 = bm + wm * 32 + mt * 16 + gid;
#pragma unroll
        for (int nt = 0; nt < 8; nt++) {
            int col = bn + wn * 64 + nt * 8 + 2 * tig;
            float2 v0 = make_float2(acc[mt][nt][0], acc[mt][nt][1]);
            float2 v1 = make_float2(acc[mt][nt][2], acc[mt][nt][3]);
            if (HAS_BIAS) {
                float bx = bias[col], by = bias[col + 1];
                v0.x += bx; v0.y += by; v1.x += bx; v1.y += by;
            }
            if (RELU_OUT) {
                v0.x = fmaxf(v0.x, 0.f); v0.y = fmaxf(v0.y, 0.f);
                v1.x = fmaxf(v1.x, 0.f); v1.y = fmaxf(v1.y, 0.f);
            }
            if (WRITE_SPLIT) {
                if (row0 < M) {
                    __nv_bfloat16* rp = Cs + (size_t)row0 * 512;
                    Pack2 h, l;
                    split_bf16(v0.x, h.h[0], l.h[0]);
                    split_bf16(v0.y, h.h[1], l.h[1]);
                    *reinterpret_cast<uint32_t*>(rp + col)       = h.u;
                    *reinterpret_cast<uint32_t*>(rp + 256 + col) = l.u;
                }
                if (row0 + 8 < M) {
                    __nv_bfloat16* rp = Cs + (size_t)(row0 + 8) * 512;
                    Pack2 h, l;
                    split_bf16(v1.x, h.h[0], l.h[0]);
                    split_bf16(v1.y, h.h[1], l.h[1]);
                    *reinterpret_cast<uint32_t*>(rp + col)       = h.u;
                    *reinterpret_cast<uint32_t*>(rp + 256 + col) = l.u;
                }
            } else {
                if (row0 < M)
                    *reinterpret_cast<float2*>(C + (size_t)row0 * 256 + col) = v0;
                if (row0 + 8 < M)
                    *reinterpret_cast<float2*>(C + (size_t)(row0 + 8) * 256 + col) = v1;
            }
        }
    }
}

// ---------------- launch ----------------------------------------------------
extern "C" void kernel_launch(void* const* d_in, const int* in_sizes, int n_in,
                              void* d_out, int out_size) {
    const float* x  = (const float*)d_in[0];
    const int*   ei = (const int*)d_in[1];
    const float* W0 = (const float*)d_in[2],  *b0 = (const float*)d_in[3];
    const float* W1 = (const float*)d_in[4],  *b1 = (const float*)d_in[5];
    const float* W2 = (const float*)d_in[6],  *b2 = (const float*)d_in[7];
    const float* M1 = (const float*)d_in[8],  *m1b = (const float*)d_in[9];
    const float* M2 = (const float*)d_in[10], *m2b = (const float*)d_in[11];
    const float* M3 = (const float*)d_in[12], *m3b = (const float*)d_in[13];
    float* out = (float*)d_out;

    float *tmp;
    __nv_bfloat16 *bufA, *bufB, *w2;
    cudaGetSymbolAddress((void**)&tmp,  g_tmp);
    cudaGetSymbolAddress((void**)&bufA, g_bufA);
    cudaGetSymbolAddress((void**)&bufB, g_bufB);
    cudaGetSymbolAddress((void**)&w2,   g_w2);

    cudaFuncSetAttribute(hgemm_kernel<false, false, false>,
                         cudaFuncAttributeMaxDynamicSharedMemorySize, SMEM_DYN);
    cudaFuncSetAttribute(hgemm_kernel<true, true, true>,
                         cudaFuncAttributeMaxDynamicSharedMemorySize, SMEM_DYN);
    cudaFuncSetAttribute(hgemm_kernel<true, false, false>,
                         cudaFuncAttributeMaxDynamicSharedMemorySize, SMEM_DYN);

    // one-time side-stream for CSR overlap (same work every call)
    static cudaStream_t s2 = nullptr;
    static cudaEvent_t  e1 = nullptr, e2 = nullptr;
    if (!s2) {
        cudaStreamCreateWithFlags(&s2, cudaStreamNonBlocking);
        cudaEventCreateWithFlags(&e1, cudaEventDisableTiming);
        cudaEventCreateWithFlags(&e2, cudaEventDisableTiming);
    }

    const int TPB = 256;
    int nb_nodes = (N_NODES + TPB - 1) / TPB;
    int nb_edges = (N_EDGES + TPB - 1) / TPB;

    // fork: CSR chain on s2, overlapped with conversions + conv0 GEMM
    cudaEventRecord(e1, 0);
    cudaStreamWaitEvent(s2, e1, 0);
    cnt_zero_kernel<<<nb_nodes, TPB, 0, s2>>>();
    hist_kernel   <<<nb_edges, TPB, 0, s2>>>(ei);
    scan_kernel   <<<1, 1024, 0, s2>>>();
    scatter_kernel<<<nb_edges, TPB, 0, s2>>>(ei);
    cudaEventRecord(e2, s2);

    wconv_kernel<<<(256 * 320 + 5 * 65536 + TPB - 1) / TPB, TPB>>>(W0, W1, W2, M1, M2, M3);
    a2x_kernel  <<<(N_NODES * 320 + TPB - 1) / TPB, TPB>>>(x, bufA);

    dim3 gg((N_NODES + 127) / 128, 2);
    int agg_blocks = (N_NODES * 32 + TPB - 1) / TPB;
    const size_t WSLOT = 163840;

    // conv0 GEMM (does not need CSR)
    hgemm_kernel<false, false, false><<<gg, TPB, SMEM_DYN>>>(bufA, w2, nullptr, tmp, nullptr, N_NODES, 320);
    // join: aggregation needs CSR
    cudaStreamWaitEvent(0, e2, 0);
    agg_kernel<1><<<agg_blocks, TPB>>>(tmp, b0, bufB);
    // conv1
    hgemm_kernel<false, false, false><<<gg, TPB, SMEM_DYN>>>(bufB, w2 + WSLOT, nullptr, tmp, nullptr, N_NODES, 256);
    agg_kernel<1><<<agg_blocks, TPB>>>(tmp, b1, bufA);
    // conv2 (no relu)
    hgemm_kernel<false, false, false><<<gg, TPB, SMEM_DYN>>>(bufA, w2 + 2 * WSLOT, nullptr, tmp, nullptr, N_NODES, 256);
    agg_kernel<0><<<agg_blocks, TPB>>>(tmp, b2, bufB);
    // MLP
    hgemm_kernel<true, true, true><<<gg, TPB, SMEM_DYN>>>(bufB, w2 + 3 * WSLOT, m1b, nullptr, bufA, N_NODES, 256);
    hgemm_kernel<true, true, true><<<gg, TPB, SMEM_DYN>>>(bufA, w2 + 4 * WSLOT, m2b, nullptr, bufB, N_NODES, 256);
    hgemm_kernel<true, false, false><<<gg, TPB, SMEM_DYN>>>(bufB, w2 + 5 * WSLOT, m3b, out, nullptr, N_NODES, 256);
}

// round 11
// speedup vs baseline: 1.1313x; 1.1313x over previous
#include <cuda_runtime.h>
#include <cuda_bf16.h>
#include <cstdint>

#define N_NODES 20000
#define N_EDGES 320000
#define D_IN    300
#define EMB     256

// ---------------- scratch (device globals; no allocation allowed) ----------
__device__ float g_tmp[N_NODES * EMB];
__device__ float g_dinv[N_NODES];
__device__ int   g_cnt [N_NODES];
__device__ int   g_rowptr[N_NODES + 1];
__device__ int   g_fill[N_NODES];
__device__ int   g_srcs[N_EDGES];
__device__ __align__(16) __nv_bfloat16 g_bufA[N_NODES * 640];
__device__ __align__(16) __nv_bfloat16 g_bufB[N_NODES * 640];
__device__ __align__(16) __nv_bfloat16 g_w2[6 * 256 * 640];

// ---------------- PTX helpers ----------------------------------------------
__device__ __forceinline__ uint32_t smem_u32(const void* p) {
    uint32_t a;
    asm("{ .reg .u64 t; cvta.to.shared.u64 t, %1; cvt.u32.u64 %0, t; }"
        : "=r"(a) : "l"(p));
    return a;
}
#define CP_ASYNC16Z(dst, src, sz) \
    asm volatile("cp.async.cg.shared.global [%0], [%1], 16, %2;" \
                 :: "r"(dst), "l"(src), "r"(sz) : "memory")
#define CP_ASYNC16(dst, src) \
    asm volatile("cp.async.cg.shared.global [%0], [%1], 16;" \
                 :: "r"(dst), "l"(src) : "memory")
#define CP_COMMIT() asm volatile("cp.async.commit_group;" ::: "memory")
#define CP_WAIT1()  asm volatile("cp.async.wait_group 1;" ::: "memory")
#define CP_WAIT0()  asm volatile("cp.async.wait_group 0;" ::: "memory")
#define LDM_X4(r0, r1, r2, r3, a) \
    asm volatile("ldmatrix.sync.aligned.m8n8.x4.shared.b16 {%0,%1,%2,%3}, [%4];" \
                 : "=r"(r0), "=r"(r1), "=r"(r2), "=r"(r3) : "r"(a))
#define MMA16816(d, a, b0v, b1v) \
    asm volatile("mma.sync.aligned.m16n8k16.row.col.f32.bf16.bf16.f32 " \
                 "{%0,%1,%2,%3},{%4,%5,%6,%7},{%8,%9},{%0,%1,%2,%3};" \
                 : "+f"((d)[0]), "+f"((d)[1]), "+f"((d)[2]), "+f"((d)[3]) \
                 : "r"((a)[0]), "r"((a)[1]), "r"((a)[2]), "r"((a)[3]), \
                   "r"(b0v), "r"(b1v))

__device__ __forceinline__ void split_bf16(float x, __nv_bfloat16& hi,
                                           __nv_bfloat16& lo) {
    hi = __float2bfloat16_rn(x);
    lo = __float2bfloat16_rn(x - __bfloat162float(hi));
}
union Pack4 { __nv_bfloat16 h[4]; uint2 u; };
union Pack2 { __nv_bfloat16 h[2]; uint32_t u; };

// ---------------- CSR build -------------------------------------------------
__global__ void cnt_zero_kernel() {
    int i = blockIdx.x * blockDim.x + threadIdx.x;
    if (i < N_NODES) g_cnt[i] = 0;
}
__global__ void hist_kernel(const int* __restrict__ ei) {
    int e = blockIdx.x * blockDim.x + threadIdx.x;
    if (e < N_EDGES) atomicAdd(&g_cnt[ei[N_EDGES + e]], 1);
}
// fast block scan: each thread serially owns 20 elements, warp-shuffle scan
__global__ void __launch_bounds__(1024) scan_kernel() {
    const int PER = 20;    // 1024*20 = 20480 >= N_NODES
    int tid = threadIdx.x;
    int lane = tid & 31, wid = tid >> 5;
    int base = tid * PER;
    int sum = 0;
#pragma unroll
    for (int i = 0; i < PER; i++) {
        int idx = base + i;
        if (idx < N_NODES) sum += g_cnt[idx];
    }
    int tot = sum;
#pragma unroll
    for (int o = 1; o < 32; o <<= 1) {
        int n = __shfl_up_sync(0xFFFFFFFFu, tot, o);
        if (lane >= o) tot += n;
    }
    __shared__ int wsum[32];
    if (lane == 31) wsum[wid] = tot;
    __syncthreads();
    if (wid == 0) {
        int v = wsum[lane];
#pragma unroll
        for (int o = 1; o < 32; o <<= 1) {
            int n = __shfl_up_sync(0xFFFFFFFFu, v, o);
            if (lane >= o) v += n;
        }
        wsum[lane] = v;
    }
    __syncthreads();
    int off = (wid ? wsum[wid - 1] : 0) + (tot - sum);  // exclusive offset
    if (tid == 0) g_rowptr[0] = 0;
    int run = off;
#pragma unroll
    for (int i = 0; i < PER; i++) {
        int idx = base + i;
        if (idx < N_NODES) {
            int v = g_cnt[idx];
            run += v;
            g_rowptr[idx + 1] = run;
            g_fill[idx]       = run - v;
            g_dinv[idx]       = rsqrtf((float)v + 1.0f);
        }
    }
}
__global__ void scatter_kernel(const int* __restrict__ ei) {
    int e = blockIdx.x * blockDim.x + threadIdx.x;
    if (e < N_EDGES) {
        int s = ei[e];
        int d = ei[N_EDGES + e];
        int pos = atomicAdd(&g_fill[d], 1);
        g_srcs[pos] = s;
    }
}

// ---------------- aggregation (pull) + fused relu + split-bf16 output ------
template<int RELU>
__global__ void __launch_bounds__(256)
agg_kernel(const float* __restrict__ tmp, const float* __restrict__ bias,
           __nv_bfloat16* __restrict__ outS) {
    int warp = (blockIdx.x * blockDim.x + threadIdx.x) >> 5;
    int lane = threadIdx.x & 31;
    if (warp >= N_NODES) return;
    float dd = g_dinv[warp];
    float ws = dd * dd;
    const float4* tp = reinterpret_cast<const float4*>(tmp);
    const float4* bp = reinterpret_cast<const float4*>(bias);
    long rb = (long)warp * 64;
    float4 b0 = bp[lane], b1 = bp[lane + 32];
    float4 t0 = tp[rb + lane], t1 = tp[rb + 32 + lane];
    float4 a0, a1;
    a0.x = fmaf(t0.x, ws, b0.x); a0.y = fmaf(t0.y, ws, b0.y);
    a0.z = fmaf(t0.z, ws, b0.z); a0.w = fmaf(t0.w, ws, b0.w);
    a1.x = fmaf(t1.x, ws, b1.x); a1.y = fmaf(t1.y, ws, b1.y);
    a1.z = fmaf(t1.z, ws, b1.z); a1.w = fmaf(t1.w, ws, b1.w);
    int e = g_rowptr[warp], end = g_rowptr[warp + 1];
    for (; e + 1 < end; e += 2) {
        int s0 = g_srcs[e], s1 = g_srcs[e + 1];
        float w0 = g_dinv[s0] * dd, w1 = g_dinv[s1] * dd;
        long sb0 = (long)s0 * 64, sb1 = (long)s1 * 64;
        float4 u0 = tp[sb0 + lane], u1 = tp[sb0 + 32 + lane];
        float4 v0 = tp[sb1 + lane], v1 = tp[sb1 + 32 + lane];
        a0.x = fmaf(u0.x, w0, a0.x); a0.y = fmaf(u0.y, w0, a0.y);
        a0.z = fmaf(u0.z, w0, a0.z); a0.w = fmaf(u0.w, w0, a0.w);
        a1.x = fmaf(u1.x, w0, a1.x); a1.y = fmaf(u1.y, w0, a1.y);
        a1.z = fmaf(u1.z, w0, a1.z); a1.w = fmaf(u1.w, w0, a1.w);
        a0.x = fmaf(v0.x, w1, a0.x); a0.y = fmaf(v0.y, w1, a0.y);
        a0.z = fmaf(v0.z, w1, a0.z); a0.w = fmaf(v0.w, w1, a0.w);
        a1.x = fmaf(v1.x, w1, a1.x); a1.y = fmaf(v1.y, w1, a1.y);
        a1.z = fmaf(v1.z, w1, a1.z); a1.w = fmaf(v1.w, w1, a1.w);
    }
    if (e < end) {
        int s0 = g_srcs[e];
        float w0 = g_dinv[s0] * dd;
        long sb0 = (long)s0 * 64;
        float4 u0 = tp[sb0 + lane], u1 = tp[sb0 + 32 + lane];
        a0.x = fmaf(u0.x, w0, a0.x); a0.y = fmaf(u0.y, w0, a0.y);
        a0.z = fmaf(u0.z, w0, a0.z); a0.w = fmaf(u0.w, w0, a0.w);
        a1.x = fmaf(u1.x, w0, a1.x); a1.y = fmaf(u1.y, w0, a1.y);
        a1.z = fmaf(u1.z, w0, a1.z); a1.w = fmaf(u1.w, w0, a1.w);
    }
    if (RELU) {
        a0.x = fmaxf(a0.x, 0.f); a0.y = fmaxf(a0.y, 0.f);
        a0.z = fmaxf(a0.z, 0.f); a0.w = fmaxf(a0.w, 0.f);
        a1.x = fmaxf(a1.x, 0.f); a1.y = fmaxf(a1.y, 0.f);
        a1.z = fmaxf(a1.z, 0.f); a1.w = fmaxf(a1.w, 0.f);
    }
    __nv_bfloat16* rp = outS + (size_t)warp * 512;
    float vs[2][4] = {{a0.x, a0.y, a0.z, a0.w}, {a1.x, a1.y, a1.z, a1.w}};
    int cols[2] = {4 * lane, 128 + 4 * lane};
#pragma unroll
    for (int h = 0; h < 2; h++) {
        Pack4 hi4, lo4;
#pragma unroll
        for (int q = 0; q < 4; q++) split_bf16(vs[h][q], hi4.h[q], lo4.h[q]);
        *reinterpret_cast<uint2*>(rp + cols[h])       = hi4.u;
        *reinterpret_cast<uint2*>(rp + 256 + cols[h]) = lo4.u;
    }
}

// ---------------- x -> split-bf16 -------------------------------------------
__global__ void a2x_kernel(const float* __restrict__ src,
                           __nv_bfloat16* __restrict__ dst) {
    const int Kp = 320;
    int idx = blockIdx.x * blockDim.x + threadIdx.x;
    if (idx >= N_NODES * Kp) return;
    int m = idx / Kp, k = idx - m * Kp;
    __nv_bfloat16 hi = __float2bfloat16_rn(0.f), lo = hi;
    if (k < D_IN) split_bf16(src[(size_t)m * D_IN + k], hi, lo);
    size_t rb = (size_t)m * 640;
    dst[rb + k]      = hi;
    dst[rb + Kp + k] = lo;
}

// ---------------- weights -> split-bf16 -------------------------------------
__global__ void wconv_kernel(const float* __restrict__ W0,
                             const float* __restrict__ W1,
                             const float* __restrict__ W2,
                             const float* __restrict__ M1,
                             const float* __restrict__ M2,
                             const float* __restrict__ M3) {
    int idx = blockIdx.x * blockDim.x + threadIdx.x;
    const float* srcs[6] = {W0, W1, W2, M1, M2, M3};
    int slot, n, k, K, Kp;
    if (idx < 256 * 320) {
        slot = 0; n = idx / 320; k = idx - n * 320; K = D_IN; Kp = 320;
    } else {
        int r = idx - 256 * 320;
        if (r >= 5 * 256 * 256) return;
        slot = 1 + r / 65536; int q = r & 65535;
        n = q >> 8; k = q & 255; K = 256; Kp = 256;
    }
    __nv_bfloat16 hi = __float2bfloat16_rn(0.f), lo = hi;
    if (k < K) split_bf16(srcs[slot][(size_t)k * 256 + n], hi, lo);
    __nv_bfloat16* dst = g_w2 + (size_t)slot * 163840 + (size_t)n * 2 * Kp;
    dst[k]      = hi;
    dst[Kp + k] = lo;
}

// ---------------- bf16 HMMA GEMM (round-9 structure: 2-stage, one-pass) -----
#define ROWB 80
#define TILEB (128 * ROWB)

template<bool HAS_BIAS, bool RELU_OUT, bool WRITE_SPLIT>
__global__ void __launch_bounds__(256)
hgemm_kernel(const __nv_bfloat16* __restrict__ A2,
             const __nv_bfloat16* __restrict__ B2,
             const float* __restrict__ bias,
             float* __restrict__ C, __nv_bfloat16* __restrict__ Cs,
             int M, int Kp) {
    __shared__ __align__(128) char sm[2][2 * TILEB];

    int tid  = threadIdx.x;
    int wid  = tid >> 5;
    int lane = tid & 31;
    int bm = blockIdx.x * 128;
    int bn = blockIdx.y * 128;
    int wm = wid & 3;
    int wn = wid >> 2;
    int nseg = Kp >> 5;
    int NK = 3 * nseg;
    int KS = 2 * Kp;

    uint32_t sbase = smem_u32(&sm[0][0]);

    auto issue = [&](int c, int buf) {
        int seg = c / nseg, kc = c - seg * nseg;
        int ka = ((seg == 1) ? Kp : 0) + kc * 32;
        int kb = ((seg == 2) ? Kp : 0) + kc * 32;
        uint32_t aB = sbase + buf * (2 * TILEB);
        uint32_t bB = aB + TILEB;
#pragma unroll
        for (int i = 0; i < 2; i++) {
            int u = tid + i * 256;
            int r = u >> 2, un = u & 3;
            uint32_t dst = aB + r * ROWB + un * 16;
            const __nv_bfloat16* src = A2 + (size_t)(bm + r) * KS + ka + un * 8;
            int sz = (bm + r < M) ? 16 : 0;
            CP_ASYNC16Z(dst, src, sz);
        }
#pragma unroll
        for (int i = 0; i < 2; i++) {
            int u = tid + i * 256;
            int r = u >> 2, un = u & 3;
            uint32_t dst = bB + r * ROWB + un * 16;
            const __nv_bfloat16* src = B2 + (size_t)(bn + r) * KS + kb + un * 8;
            CP_ASYNC16(dst, src);
        }
        CP_COMMIT();
    };

    float acc[2][8][4];
#pragma unroll
    for (int mt = 0; mt < 2; mt++)
#pragma unroll
        for (int nt = 0; nt < 8; nt++)
#pragma unroll
            for (int q = 0; q < 4; q++) acc[mt][nt][q] = 0.f;

    issue(0, 0);
    for (int c = 0; c < NK; c++) {
        if (c + 1 < NK) { issue(c + 1, (c + 1) & 1); CP_WAIT1(); }
        else            { CP_WAIT0(); }
        __syncthreads();

        uint32_t aB = sbase + (c & 1) * (2 * TILEB);
        uint32_t bB = aB + TILEB;

        uint32_t breg[8][4];
#pragma unroll
        for (int nt = 0; nt < 8; nt++) {
            uint32_t addr = bB + (uint32_t)((wn * 64 + nt * 8 + (lane & 7)) * ROWB
                                            + (lane >> 3) * 16);
            LDM_X4(breg[nt][0], breg[nt][1], breg[nt][2], breg[nt][3], addr);
        }
#pragma unroll
        for (int kt = 0; kt < 2; kt++) {
            uint32_t areg[2][4];
#pragma unroll
            for (int mt = 0; mt < 2; mt++) {
                uint32_t addr = aB + (uint32_t)((wm * 32 + mt * 16 + (lane & 15)) * ROWB
                                                + (kt * 2 + (lane >> 4)) * 16);
                LDM_X4(areg[mt][0], areg[mt][1], areg[mt][2], areg[mt][3], addr);
            }
#pragma unroll
            for (int mt = 0; mt < 2; mt++)
#pragma unroll
                for (int nt = 0; nt < 8; nt++)
                    MMA16816(acc[mt][nt], areg[mt],
                             breg[nt][kt * 2], breg[nt][kt * 2 + 1]);
        }
        __syncthreads();
    }

    // epilogue
    int gid = lane >> 2, tig = lane & 3;
#pragma unroll
    for (int mt = 0; mt < 2; mt++) {
        int row0 = bm + wm * 32 + mt * 16 + gid;
#pragma unroll
        for (int nt = 0; nt < 8; nt++) {
            int col = bn + wn * 64 + nt * 8 + 2 * tig;
            float2 v0 = make_float2(acc[mt][nt][0], acc[mt][nt][1]);
            float2 v1 = make_float2(acc[mt][nt][2], acc[mt][nt][3]);
            if (HAS_BIAS) {
                float bx = bias[col], by = bias[col + 1];
                v0.x += bx; v0.y += by; v1.x += bx; v1.y += by;
            }
            if (RELU_OUT) {
                v0.x = fmaxf(v0.x, 0.f); v0.y = fmaxf(v0.y, 0.f);
                v1.x = fmaxf(v1.x, 0.f); v1.y = fmaxf(v1.y, 0.f);
            }
            if (WRITE_SPLIT) {
                if (row0 < M) {
                    __nv_bfloat16* rp = Cs + (size_t)row0 * 512;
                    Pack2 h, l;
                    split_bf16(v0.x, h.h[0], l.h[0]);
                    split_bf16(v0.y, h.h[1], l.h[1]);
                    *reinterpret_cast<uint32_t*>(rp + col)       = h.u;
                    *reinterpret_cast<uint32_t*>(rp + 256 + col) = l.u;
                }
                if (row0 + 8 < M) {
                    __nv_bfloat16* rp = Cs + (size_t)(row0 + 8) * 512;
                    Pack2 h, l;
                    split_bf16(v1.x, h.h[0], l.h[0]);
                    split_bf16(v1.y, h.h[1], l.h[1]);
                    *reinterpret_cast<uint32_t*>(rp + col)       = h.u;
                    *reinterpret_cast<uint32_t*>(rp + 256 + col) = l.u;
                }
            } else {
                if (row0 < M)
                    *reinterpret_cast<float2*>(C + (size_t)row0 * 256 + col) = v0;
                if (row0 + 8 < M)
                    *reinterpret_cast<float2*>(C + (size_t)(row0 + 8) * 256 + col) = v1;
            }
        }
    }
}

// ---------------- launch ----------------------------------------------------
extern "C" void kernel_launch(void* const* d_in, const int* in_sizes, int n_in,
                              void* d_out, int out_size) {
    const float* x  = (const float*)d_in[0];
    const int*   ei = (const int*)d_in[1];
    const float* W0 = (const float*)d_in[2],  *b0 = (const float*)d_in[3];
    const float* W1 = (const float*)d_in[4],  *b1 = (const float*)d_in[5];
    const float* W2 = (const float*)d_in[6],  *b2 = (const float*)d_in[7];
    const float* M1 = (const float*)d_in[8],  *m1b = (const float*)d_in[9];
    const float* M2 = (const float*)d_in[10], *m2b = (const float*)d_in[11];
    const float* M3 = (const float*)d_in[12], *m3b = (const float*)d_in[13];
    float* out = (float*)d_out;

    float *tmp;
    __nv_bfloat16 *bufA, *bufB, *w2;
    cudaGetSymbolAddress((void**)&tmp,  g_tmp);
    cudaGetSymbolAddress((void**)&bufA, g_bufA);
    cudaGetSymbolAddress((void**)&bufB, g_bufB);
    cudaGetSymbolAddress((void**)&w2,   g_w2);

    // one-time side-stream for CSR overlap (same work every call)
    static cudaStream_t s2 = nullptr;
    static cudaEvent_t  e1 = nullptr, e2 = nullptr;
    if (!s2) {
        cudaStreamCreateWithFlags(&s2, cudaStreamNonBlocking);
        cudaEventCreateWithFlags(&e1, cudaEventDisableTiming);
        cudaEventCreateWithFlags(&e2, cudaEventDisableTiming);
    }

    const int TPB = 256;
    int nb_nodes = (N_NODES + TPB - 1) / TPB;
    int nb_edges = (N_EDGES + TPB - 1) / TPB;

    // fork: CSR chain on s2, overlapped with conversions + conv0 GEMM
    cudaEventRecord(e1, 0);
    cudaStreamWaitEvent(s2, e1, 0);
    cnt_zero_kernel<<<nb_nodes, TPB, 0, s2>>>();
    hist_kernel   <<<nb_edges, TPB, 0, s2>>>(ei);
    scan_kernel   <<<1, 1024, 0, s2>>>();
    scatter_kernel<<<nb_edges, TPB, 0, s2>>>(ei);
    cudaEventRecord(e2, s2);

    wconv_kernel<<<(256 * 320 + 5 * 65536 + TPB - 1) / TPB, TPB>>>(W0, W1, W2, M1, M2, M3);
    a2x_kernel  <<<(N_NODES * 320 + TPB - 1) / TPB, TPB>>>(x, bufA);

    dim3 gg((N_NODES + 127) / 128, 2);
    int agg_blocks = (N_NODES * 32 + TPB - 1) / TPB;
    const size_t WSLOT = 163840;

    // conv0 GEMM (does not need CSR)
    hgemm_kernel<false, false, false><<<gg, TPB>>>(bufA, w2, nullptr, tmp, nullptr, N_NODES, 320);
    // join: aggregation needs CSR
    cudaStreamWaitEvent(0, e2, 0);
    agg_kernel<1><<<agg_blocks, TPB>>>(tmp, b0, bufB);
    // conv1
    hgemm_kernel<false, false, false><<<gg, TPB>>>(bufB, w2 + WSLOT, nullptr, tmp, nullptr, N_NODES, 256);
    agg_kernel<1><<<agg_blocks, TPB>>>(tmp, b1, bufA);
    // conv2 (no relu)
    hgemm_kernel<false, false, false><<<gg, TPB>>>(bufA, w2 + 2 * WSLOT, nullptr, tmp, nullptr, N_NODES, 256);
    agg_kernel<0><<<agg_blocks, TPB>>>(tmp, b2, bufB);
    // MLP
    hgemm_kernel<true, true, true><<<gg, TPB>>>(bufB, w2 + 3 * WSLOT, m1b, nullptr, bufA, N_NODES, 256);
    hgemm_kernel<true, true, true><<<gg, TPB>>>(bufA, w2 + 4 * WSLOT, m2b, nullptr, bufB, N_NODES, 256);
    hgemm_kernel<true, false, false><<<gg, TPB>>>(bufB, w2 + 5 * WSLOT, m3b, out, nullptr, N_NODES, 256);
}